// round 15
// baseline (speedup 1.0000x reference)
#include <cuda_runtime.h>
#include <cuda_fp16.h>
#include <cstdint>

#define NLAYERS 6
#define Fdim 512
#define Hh 8
#define DHd 64
#define MTOK (64*512)        /* 32768 tokens */
#define Sseq 512
#define EPSF 1e-5f
#define WMAT (Fdim*Fdim)
#define WSCALE 256.0f
#define INV_WSCALE (1.0f/256.0f)

/* ---- warp-MMA GEMM config: 128x128 block, 4 warps of 64x64 ---- */
#define BK 32
#define KITERS (Fdim/BK)     /* 16 */
#define ROWB 80              /* 32 fp16 = 64B data + 16B pad per row */
#define TILESM (128*ROWB)    /* 10240 B */
#define STAGE3 (3*TILESM)    /* A, Bh, Bl = 30720 B */
#define GSMEM (3*STAGE3)     /* 92160 B; x2 CTAs/SM = 184320 < 228KB */
#define OFF_A 0
#define OFF_BH TILESM
#define OFF_BL (2*TILESM)

/* ---- scratch (allocation-free) ---- */
__device__ __align__(256) float g_q[MTOK*Fdim];
__device__ __align__(256) float g_k[MTOK*Fdim];
__device__ __align__(256) float g_v[MTOK*Fdim];
__device__ __align__(256) float g_y[MTOK*Fdim];
__device__ __align__(256) __half g_xh[MTOK*Fdim];   /* fp16(x) — GEMM operand */
__device__ __align__(256) __half g_xl[MTOK*Fdim];   /* fp16(x - xh) — resid only */
__device__ __align__(256) __half g_wh[NLAYERS*4*WMAT];  /* fp16(256*W), [N,K] */
__device__ __align__(256) __half g_wl[NLAYERS*4*WMAT];  /* fp16(256*W - Wh)    */

/* ---------------- PTX helpers (all sm_80+ baseline) ---------------- */
#define CP16(s,g) asm volatile("cp.async.cg.shared.global [%0], [%1], 16;" \
                               :: "r"(s), "l"(g))
#define CPCOMMIT() asm volatile("cp.async.commit_group;" ::: "memory")
#define CPWAIT(n)  asm volatile("cp.async.wait_group %0;" :: "n"(n) : "memory")

#define LDSM4(r, a) \
    asm volatile("ldmatrix.sync.aligned.m8n8.x4.shared.b16 {%0,%1,%2,%3}, [%4];" \
        : "=r"((r)[0]), "=r"((r)[1]), "=r"((r)[2]), "=r"((r)[3]) : "r"(a))

#define MMA(c, a, b0, b1) \
    asm volatile("mma.sync.aligned.m16n8k16.row.col.f32.f16.f16.f32 " \
        "{%0,%1,%2,%3}, {%4,%5,%6,%7}, {%8,%9}, {%0,%1,%2,%3};" \
        : "+f"((c)[0]), "+f"((c)[1]), "+f"((c)[2]), "+f"((c)[3]) \
        : "r"((a)[0]), "r"((a)[1]), "r"((a)[2]), "r"((a)[3]), "r"(b0), "r"(b1))

/* ---------------- fp16 2-term warp-MMA GEMM ----------------
   C[128,128] = (1/256) * A16[*,512] @ (Wh+Wl)^T + bias (+ recombined resid)
   A row-major fp16, W K-major [N,K] fp16 pre-scaled by 256.  3-stage cp.async.
   128 threads; 4 warps each own a 64x64 output tile. */
__device__ __forceinline__ void load_stage(
    uint32_t tb, const __half* __restrict__ A,
    const __half* __restrict__ Bh, const __half* __restrict__ Bl,
    int m0, int n0, int kc, int tid)
{
    #pragma unroll
    for (int idx = tid; idx < 512; idx += 128) {
        const int r = idx >> 2, p = idx & 3;
        const uint32_t so = (uint32_t)(r*ROWB + p*16);
        const size_t ka = (size_t)(m0 + r)*Fdim + kc*BK + p*8;
        const size_t kb = (size_t)(n0 + r)*Fdim + kc*BK + p*8;
        CP16(tb + OFF_A  + so, A  + ka);
        CP16(tb + OFF_BH + so, Bh + kb);
        CP16(tb + OFF_BL + so, Bl + kb);
    }
    CPCOMMIT();
}

__device__ __forceinline__ void gemm_mma(
    const __half* __restrict__ A,
    const __half* __restrict__ Bh, const __half* __restrict__ Bl,
    const float* __restrict__ bias,
    const __half* __restrict__ residh, const __half* __restrict__ residl,
    float* __restrict__ C)
{
    extern __shared__ char ds[];
    const uint32_t sb = (uint32_t)__cvta_generic_to_shared(ds);
    const int tid = threadIdx.x, l = tid & 31, wid = tid >> 5;
    const int wm = wid & 1, wn = wid >> 1;          /* warps: 2 (M) x 2 (N) */
    const int m0 = blockIdx.y * 128, n0 = blockIdx.x * 128;

    /* ldmatrix per-lane offsets */
    const uint32_t aoff = (uint32_t)((l & 15)*ROWB + (l >> 4)*16);
    const uint32_t boff = (uint32_t)(((l & 7) + ((l >> 4) << 3))*ROWB + ((l >> 3) & 1)*16);
    const uint32_t awarp = (uint32_t)(wm*64*ROWB);
    const uint32_t bwarp = (uint32_t)(wn*64*ROWB);

    float acc[4][8][4];
    #pragma unroll
    for (int i = 0; i < 4; i++)
        #pragma unroll
        for (int j = 0; j < 8; j++)
            #pragma unroll
            for (int t = 0; t < 4; t++) acc[i][j][t] = 0.f;

    /* prologue: stages 0,1 */
    load_stage(sb + 0*STAGE3, A, Bh, Bl, m0, n0, 0, tid);
    load_stage(sb + 1*STAGE3, A, Bh, Bl, m0, n0, 1, tid);

    int bufc = 0;   /* (kc)%3 */
    int bufn = 2;   /* (kc+2)%3 */
    for (int kc = 0; kc < KITERS; kc++) {
        if (kc < KITERS-1) { CPWAIT(1); } else { CPWAIT(0); }
        __syncthreads();   /* also separates prev compute from new stores */
        if (kc + 2 < KITERS)
            load_stage(sb + bufn*STAGE3, A, Bh, Bl, m0, n0, kc+2, tid);

        const uint32_t tb = sb + bufc*STAGE3;
        #pragma unroll
        for (int ks = 0; ks < 2; ks++) {
            const uint32_t kso = (uint32_t)(ks*32);   /* 16 fp16 = 32 B */
            uint32_t ah[4][4], bb[4][4];
            #pragma unroll
            for (int mf = 0; mf < 4; mf++)
                LDSM4(ah[mf], tb + OFF_A + awarp + (uint32_t)(mf*16*ROWB) + kso + aoff);
            /* hi term */
            #pragma unroll
            for (int nb = 0; nb < 4; nb++)
                LDSM4(bb[nb], tb + OFF_BH + bwarp + (uint32_t)(nb*16*ROWB) + kso + boff);
            #pragma unroll
            for (int mf = 0; mf < 4; mf++)
                #pragma unroll
                for (int nb = 0; nb < 4; nb++) {
                    MMA(acc[mf][nb*2+0], ah[mf], bb[nb][0], bb[nb][1]);
                    MMA(acc[mf][nb*2+1], ah[mf], bb[nb][2], bb[nb][3]);
                }
            /* lo term */
            #pragma unroll
            for (int nb = 0; nb < 4; nb++)
                LDSM4(bb[nb], tb + OFF_BL + bwarp + (uint32_t)(nb*16*ROWB) + kso + boff);
            #pragma unroll
            for (int mf = 0; mf < 4; mf++)
                #pragma unroll
                for (int nb = 0; nb < 4; nb++) {
                    MMA(acc[mf][nb*2+0], ah[mf], bb[nb][0], bb[nb][1]);
                    MMA(acc[mf][nb*2+1], ah[mf], bb[nb][2], bb[nb][3]);
                }
        }
        bufc = (bufc == 2) ? 0 : bufc + 1;
        bufn = (bufn == 2) ? 0 : bufn + 1;
    }

    /* epilogue: scale + bias (+ split resid) */
    #pragma unroll
    for (int mf = 0; mf < 4; mf++) {
        #pragma unroll
        for (int half = 0; half < 2; half++) {
            const int row = m0 + wm*64 + mf*16 + half*8 + (l >> 2);
            const size_t ro = (size_t)row * Fdim;
            #pragma unroll
            for (int nf = 0; nf < 8; nf++) {
                const int col = n0 + wn*64 + nf*8 + (l & 3)*2;
                float2 o;
                o.x = acc[mf][nf][half*2+0]*INV_WSCALE + bias[col];
                o.y = acc[mf][nf][half*2+1]*INV_WSCALE + bias[col+1];
                if (residh) {
                    const __half2 rh = *(const __half2*)(residh + ro + col);
                    const __half2 rl = *(const __half2*)(residl + ro + col);
                    const float2 fh = __half22float2(rh);
                    const float2 fl = __half22float2(rl);
                    o.x += fh.x + fl.x; o.y += fh.y + fl.y;
                }
                *(float2*)(C + ro + col) = o;
            }
        }
    }
}

__global__ __launch_bounds__(128, 2)
void qkv_gemm(const __half* __restrict__ xh,
              const __half* __restrict__ wh, const __half* __restrict__ wl,
              const float* __restrict__ bq, const float* __restrict__ bk,
              const float* __restrict__ bv,
              float* __restrict__ Q, float* __restrict__ K, float* __restrict__ V)
{
    const int z = blockIdx.z;
    const __half* Bh = wh + (size_t)z*WMAT;
    const __half* Bl = wl + (size_t)z*WMAT;
    const float* bias = (z == 0) ? bq : (z == 1) ? bk : bv;
    float* C = (z == 0) ? Q : (z == 1) ? K : V;
    gemm_mma(xh, Bh, Bl, bias, nullptr, nullptr, C);
}

__global__ __launch_bounds__(128, 2)
void ff_gemm(const __half* __restrict__ xh, const __half* __restrict__ xl,
             const __half* __restrict__ wh, const __half* __restrict__ wl,
             const float* __restrict__ bf, float* __restrict__ Y)
{
    gemm_mma(xh, wh, wl, bf, xh, xl, Y);   /* resid = recombined x */
}

/* ------ one-shot weight transpose + scaled fp16 split: W[k,n] -> [n,k] ------ */
__global__ __launch_bounds__(256)
void wconv_kernel(const float* __restrict__ Wq, const float* __restrict__ Wk,
                  const float* __restrict__ Wv, const float* __restrict__ Wf,
                  __half* __restrict__ oh, __half* __restrict__ ol)
{
    __shared__ float tile[32][33];
    const int z = blockIdx.z, layer = z >> 2, mat = z & 3;
    const float* W = ((mat == 0) ? Wq : (mat == 1) ? Wk : (mat == 2) ? Wv : Wf)
                     + (size_t)layer*WMAT;
    const int kx = blockIdx.x*32, ny = blockIdx.y*32;
    const int ix = threadIdx.x & 31, iy = threadIdx.x >> 5;  /* 32 x 8 */
    #pragma unroll
    for (int j = 0; j < 4; j++)
        tile[iy + 8*j][ix] = W[(size_t)(kx + iy + 8*j)*Fdim + ny + ix];
    __syncthreads();
    __half* dh = oh + (size_t)z*WMAT;
    __half* dl = ol + (size_t)z*WMAT;
    #pragma unroll
    for (int j = 0; j < 4; j++) {
        const float v = tile[ix][iy + 8*j] * WSCALE;
        const __half h = __float2half(v);
        const float lo = v - __half2float(h);
        const size_t o = (size_t)(ny + iy + 8*j)*Fdim + kx + ix;
        dh[o] = h; dl[o] = __float2half(lo);
    }
}

/* ---------------- fp16 split store / recombine helpers ---------------- */
__device__ __forceinline__ void store_split4(__half* hi, __half* lo,
                                             size_t base, float4 o)
{
    const __half h0=__float2half(o.x), h1=__float2half(o.y),
                 h2=__float2half(o.z), h3=__float2half(o.w);
    __half2 hp0 = __halves2half2(h0,h1), hp1 = __halves2half2(h2,h3);
    __half2 lp0 = __halves2half2(__float2half(o.x-__half2float(h0)),
                                 __float2half(o.y-__half2float(h1)));
    __half2 lp1 = __halves2half2(__float2half(o.z-__half2float(h2)),
                                 __float2half(o.w-__half2float(h3)));
    uint2 hu, lu;
    hu.x = reinterpret_cast<uint32_t&>(hp0); hu.y = reinterpret_cast<uint32_t&>(hp1);
    lu.x = reinterpret_cast<uint32_t&>(lp0); lu.y = reinterpret_cast<uint32_t&>(lp1);
    *(uint2*)(hi + base) = hu; *(uint2*)(lo + base) = lu;
}

__device__ __forceinline__ float4 load_recombine4(const __half* hi,
                                                  const __half* lo, size_t base)
{
    const uint2 hu = *(const uint2*)(hi + base);
    const uint2 lu = *(const uint2*)(lo + base);
    const float2 f0 = __half22float2(reinterpret_cast<const __half2&>(hu.x));
    const float2 f1 = __half22float2(reinterpret_cast<const __half2&>(hu.y));
    const float2 g0 = __half22float2(reinterpret_cast<const __half2&>(lu.x));
    const float2 g1 = __half22float2(reinterpret_cast<const __half2&>(lu.y));
    return make_float4(f0.x+g0.x, f0.y+g0.y, f1.x+g1.x, f1.y+g1.y);
}

/* ------- attention + residual + LN1, 2 tokens per 256-thread block ------- */
__global__ __launch_bounds__(256)
void attn_ln_kernel(const float* __restrict__ Q, const float* __restrict__ Km,
                    const float* __restrict__ V,
                    const float* __restrict__ gma, const float* __restrict__ bta,
                    __half* __restrict__ xh, __half* __restrict__ xl)
{
    __shared__ __align__(16) float sk[2][Fdim], sv[2][Fdim];
    __shared__ float red[2][2][4];
    const int tid = threadIdx.x;
    const int half = tid >> 7;
    const int t = tid & 127;
    const int m = blockIdx.x*2 + half;
    const size_t off = (size_t)m * Fdim;

    const float4 qreg = *(const float4*)(Q + off + 4*t);
    ((float4*)sk[half])[t] = *(const float4*)(Km + off + 4*t);
    ((float4*)sv[half])[t] = *(const float4*)(V  + off + 4*t);
    const float4 xr = load_recombine4(xh, xl, off + 4*t);
    __syncthreads();

    const int dbase = (t & 15) * 4;
    float sc[Hh];
    #pragma unroll
    for (int g = 0; g < Hh; g++) {
        const float4 kv = *(const float4*)&sk[half][g*DHd + dbase];
        float d = qreg.x*kv.x + qreg.y*kv.y + qreg.z*kv.z + qreg.w*kv.w;
        d += __shfl_xor_sync(0xffffffffu, d, 1);
        d += __shfl_xor_sync(0xffffffffu, d, 2);
        d += __shfl_xor_sync(0xffffffffu, d, 4);
        d += __shfl_xor_sync(0xffffffffu, d, 8);
        sc[g] = d;
    }
    float mx = sc[0];
    #pragma unroll
    for (int g = 1; g < Hh; g++) mx = fmaxf(mx, sc[g]);
    float sum = 0.f;
    #pragma unroll
    for (int g = 0; g < Hh; g++) { sc[g] = __expf(sc[g] - mx); sum += sc[g]; }
    const float inv = 1.f / sum;

    float4 av = make_float4(0.f, 0.f, 0.f, 0.f);
    #pragma unroll
    for (int g = 0; g < Hh; g++) {
        const float w = sc[g] * inv;
        const float4 vv = *(const float4*)&sv[half][g*DHd + dbase];
        av.x += w*vv.x; av.y += w*vv.y; av.z += w*vv.z; av.w += w*vv.w;
    }
    const float v0 = av.x+xr.x, v1 = av.y+xr.y, v2 = av.z+xr.z, v3 = av.w+xr.w;

    float lsum = v0+v1+v2+v3, lsq = v0*v0+v1*v1+v2*v2+v3*v3;
    #pragma unroll
    for (int o = 16; o > 0; o >>= 1) {
        lsum += __shfl_xor_sync(0xffffffffu, lsum, o);
        lsq  += __shfl_xor_sync(0xffffffffu, lsq,  o);
    }
    if ((t & 31) == 0) { red[half][0][t>>5] = lsum; red[half][1][t>>5] = lsq; }
    __syncthreads();
    const float tsum = red[half][0][0]+red[half][0][1]+red[half][0][2]+red[half][0][3];
    const float tsq  = red[half][1][0]+red[half][1][1]+red[half][1][2]+red[half][1][3];
    const float mean = tsum * (1.f/Fdim);
    const float var  = tsq * (1.f/Fdim) - mean*mean;
    const float rstd = rsqrtf(var + EPSF);

    const float4 gm = *(const float4*)(gma + 4*t);
    const float4 bt = *(const float4*)(bta + 4*t);
    float4 o;
    o.x = (v0-mean)*rstd*gm.x + bt.x;
    o.y = (v1-mean)*rstd*gm.y + bt.y;
    o.z = (v2-mean)*rstd*gm.z + bt.z;
    o.w = (v3-mean)*rstd*gm.w + bt.w;
    store_split4(xh, xl, off + 4*t, o);
}

/* ---------------- LN2: y -> split x (or fp32 d_out on last layer) ------------- */
__global__ __launch_bounds__(128)
void ln_kernel(const float* __restrict__ Y, float* __restrict__ O,
               const float* __restrict__ gma, const float* __restrict__ bta,
               __half* __restrict__ xh, __half* __restrict__ xl)
{
    __shared__ float red[2][4];
    const int m = blockIdx.x, t = threadIdx.x;
    const size_t off = (size_t)m * Fdim;
    const float4 v = *(const float4*)(Y + off + 4*t);

    float lsum = v.x+v.y+v.z+v.w, lsq = v.x*v.x+v.y*v.y+v.z*v.z+v.w*v.w;
    #pragma unroll
    for (int o = 16; o > 0; o >>= 1) {
        lsum += __shfl_xor_sync(0xffffffffu, lsum, o);
        lsq  += __shfl_xor_sync(0xffffffffu, lsq,  o);
    }
    if ((t & 31) == 0) { red[0][t>>5] = lsum; red[1][t>>5] = lsq; }
    __syncthreads();
    const float tsum = red[0][0]+red[0][1]+red[0][2]+red[0][3];
    const float tsq  = red[1][0]+red[1][1]+red[1][2]+red[1][3];
    const float mean = tsum * (1.f/Fdim);
    const float var  = tsq * (1.f/Fdim) - mean*mean;
    const float rstd = rsqrtf(var + EPSF);

    const float4 gm = *(const float4*)(gma + 4*t);
    const float4 bt = *(const float4*)(bta + 4*t);
    float4 o;
    o.x = (v.x-mean)*rstd*gm.x + bt.x;
    o.y = (v.y-mean)*rstd*gm.y + bt.y;
    o.z = (v.z-mean)*rstd*gm.z + bt.z;
    o.w = (v.w-mean)*rstd*gm.w + bt.w;
    if (O) *(float4*)(O + off + 4*t) = o;
    if (xh) store_split4(xh, xl, off + 4*t, o);
}

/* ---------------- embedding + pos-enc -> split x ---------------- */
__global__ __launch_bounds__(128)
void embed_kernel(const int* __restrict__ text, const float* __restrict__ emb,
                  const float* __restrict__ pe,
                  __half* __restrict__ xh, __half* __restrict__ xl)
{
    const int m = blockIdx.x, t = threadIdx.x;
    const int tok = text[m];
    const int s = m & (Sseq - 1);
    const float4 e = *(const float4*)(emb + (size_t)tok*Fdim + 4*t);
    const float4 p = *(const float4*)(pe  + (size_t)s  *Fdim + 4*t);
    float4 o; o.x=e.x+p.x; o.y=e.y+p.y; o.z=e.z+p.z; o.w=e.w+p.w;
    store_split4(xh, xl, (size_t)m*Fdim + 4*t, o);
}

/* ---------------------------------------------------------------- */
extern "C" void kernel_launch(void* const* d_in, const int* in_sizes, int n_in,
                              void* d_out, int out_size)
{
    const int*   text  = (const int*)  d_in[0];
    const float* emb   = (const float*)d_in[1];
    const float* pe    = (const float*)d_in[2];
    const float* Wq    = (const float*)d_in[3];
    const float* bq    = (const float*)d_in[4];
    const float* Wk    = (const float*)d_in[5];
    const float* bk    = (const float*)d_in[6];
    const float* Wv    = (const float*)d_in[7];
    const float* bv    = (const float*)d_in[8];
    const float* g1    = (const float*)d_in[9];
    const float* beta1 = (const float*)d_in[10];
    const float* Wf    = (const float*)d_in[11];
    const float* bf    = (const float*)d_in[12];
    const float* g2    = (const float*)d_in[13];
    const float* beta2 = (const float*)d_in[14];

    float *q, *k, *v, *y;
    __half *xh, *xl, *wh, *wl;
    cudaGetSymbolAddress((void**)&q,  g_q);
    cudaGetSymbolAddress((void**)&k,  g_k);
    cudaGetSymbolAddress((void**)&v,  g_v);
    cudaGetSymbolAddress((void**)&y,  g_y);
    cudaGetSymbolAddress((void**)&xh, g_xh);
    cudaGetSymbolAddress((void**)&xl, g_xl);
    cudaGetSymbolAddress((void**)&wh, g_wh);
    cudaGetSymbolAddress((void**)&wl, g_wl);

    cudaFuncSetAttribute(qkv_gemm, cudaFuncAttributeMaxDynamicSharedMemorySize, GSMEM);
    cudaFuncSetAttribute(ff_gemm,  cudaFuncAttributeMaxDynamicSharedMemorySize, GSMEM);

    wconv_kernel<<<dim3(16,16,24), 256>>>(Wq, Wk, Wv, Wf, wh, wl);
    embed_kernel<<<MTOK, 128>>>(text, emb, pe, xh, xl);

    const dim3 gq(Fdim/128, MTOK/128, 3);
    const dim3 gf(Fdim/128, MTOK/128, 1);
    for (int i = 0; i < NLAYERS; i++) {
        const size_t wo = (size_t)i * 4 * WMAT;
        const size_t vo = (size_t)i * Fdim;
        const bool last = (i == NLAYERS-1);
        qkv_gemm<<<gq, 128, GSMEM>>>(xh, wh + wo, wl + wo,
                                     bq+vo, bk+vo, bv+vo, q, k, v);
        attn_ln_kernel<<<MTOK/2, 256>>>(q, k, v, g1+vo, beta1+vo, xh, xl);
        ff_gemm<<<gf, 128, GSMEM>>>(xh, xl, wh + wo + 3*(size_t)WMAT,
                                    wl + wo + 3*(size_t)WMAT, bf+vo, y);
        ln_kernel<<<MTOK, 128>>>(y, last ? (float*)d_out : nullptr, g2+vo, beta2+vo,
                                 last ? nullptr : xh, last ? nullptr : xl);
    }
}

// round 16
// speedup vs baseline: 1.0606x; 1.0606x over previous
#include <cuda_runtime.h>
#include <cuda_fp16.h>
#include <cstdint>

#define NLAYERS 6
#define Fdim 512
#define Hh 8
#define DHd 64
#define MTOK (64*512)        /* 32768 tokens */
#define Sseq 512
#define EPSF 1e-5f
#define WMAT (Fdim*Fdim)
#define WSCALE 256.0f
#define INV_WSCALE (1.0f/256.0f)

/* ---- warp-MMA GEMM config: 128x128 block, 8 warps of 64x32 (R13 proven) ---- */
#define BK 32
#define KITERS (Fdim/BK)     /* 16 */
#define ROWB 80              /* 32 fp16 = 64B data + 16B pad per row */
#define TILESM (128*ROWB)    /* 10240 B */
#define STAGE3 (3*TILESM)    /* A, Bh, Bl = 30720 B */
#define GSMEM (3*STAGE3)     /* 92160 B; x2 CTAs/SM = 184320 < 228KB */
#define OFF_A 0
#define OFF_BH TILESM
#define OFF_BL (2*TILESM)

/* ---- scratch (allocation-free) ---- */
__device__ __align__(256) __half g_q[MTOK*Fdim];   /* fp16 Q */
__device__ __align__(256) __half g_k[MTOK*Fdim];   /* fp16 K */
__device__ __align__(256) float  g_v[MTOK*Fdim];   /* fp32 V (linear path) */
__device__ __align__(256) float  g_y[MTOK*Fdim];
__device__ __align__(256) __half g_xh[MTOK*Fdim];  /* fp16(x) — GEMM operand */
__device__ __align__(256) __half g_xl[MTOK*Fdim];  /* fp16(x - xh) — resid only */
__device__ __align__(256) __half g_wh[NLAYERS*4*WMAT];  /* fp16(256*W), [N,K] */
__device__ __align__(256) __half g_wl[NLAYERS*4*WMAT];  /* fp16(256*W - Wh)    */

/* ---------------- PTX helpers (all sm_80+ baseline) ---------------- */
#define CP16(s,g) asm volatile("cp.async.cg.shared.global [%0], [%1], 16;" \
                               :: "r"(s), "l"(g))
#define CPCOMMIT() asm volatile("cp.async.commit_group;" ::: "memory")
#define CPWAIT(n)  asm volatile("cp.async.wait_group %0;" :: "n"(n) : "memory")

#define LDSM4(r, a) \
    asm volatile("ldmatrix.sync.aligned.m8n8.x4.shared.b16 {%0,%1,%2,%3}, [%4];" \
        : "=r"((r)[0]), "=r"((r)[1]), "=r"((r)[2]), "=r"((r)[3]) : "r"(a))

#define MMA(c, a, b0, b1) \
    asm volatile("mma.sync.aligned.m16n8k16.row.col.f32.f16.f16.f32 " \
        "{%0,%1,%2,%3}, {%4,%5,%6,%7}, {%8,%9}, {%0,%1,%2,%3};" \
        : "+f"((c)[0]), "+f"((c)[1]), "+f"((c)[2]), "+f"((c)[3]) \
        : "r"((a)[0]), "r"((a)[1]), "r"((a)[2]), "r"((a)[3]), "r"(b0), "r"(b1))

/* ---------------- fp16 2-term warp-MMA GEMM ----------------
   out = (1/256) * A16[*,512] @ (Wh+Wl)^T + bias (+ recombined resid)
   Writes fp32 to Cf, or fp16 to Ch (exactly one non-null). */
__device__ __forceinline__ void load_stage(
    uint32_t tb, const __half* __restrict__ A,
    const __half* __restrict__ Bh, const __half* __restrict__ Bl,
    int m0, int n0, int kc, int tid)
{
    #pragma unroll
    for (int idx = tid; idx < 512; idx += 256) {
        const int r = idx >> 2, p = idx & 3;
        const uint32_t so = (uint32_t)(r*ROWB + p*16);
        const size_t ka = (size_t)(m0 + r)*Fdim + kc*BK + p*8;
        const size_t kb = (size_t)(n0 + r)*Fdim + kc*BK + p*8;
        CP16(tb + OFF_A  + so, A  + ka);
        CP16(tb + OFF_BH + so, Bh + kb);
        CP16(tb + OFF_BL + so, Bl + kb);
    }
    CPCOMMIT();
}

__device__ __forceinline__ void gemm_mma(
    const __half* __restrict__ A,
    const __half* __restrict__ Bh, const __half* __restrict__ Bl,
    const float* __restrict__ bias,
    const __half* __restrict__ residh, const __half* __restrict__ residl,
    float* __restrict__ Cf, __half* __restrict__ Ch)
{
    extern __shared__ char ds[];
    const uint32_t sb = (uint32_t)__cvta_generic_to_shared(ds);
    const int tid = threadIdx.x, l = tid & 31, wid = tid >> 5;
    const int wm = wid & 1, wn = wid >> 1;          /* warps: 2 (M) x 4 (N) */
    const int m0 = blockIdx.y * 128, n0 = blockIdx.x * 128;

    /* ldmatrix per-lane offsets */
    const uint32_t aoff = (uint32_t)((l & 15)*ROWB + (l >> 4)*16);
    const uint32_t boff = (uint32_t)(((l & 7) + ((l >> 4) << 3))*ROWB + ((l >> 3) & 1)*16);
    const uint32_t awarp = (uint32_t)(wm*64*ROWB);
    const uint32_t bwarp = (uint32_t)(wn*32*ROWB);

    float acc[4][4][4];
    #pragma unroll
    for (int i = 0; i < 4; i++)
        #pragma unroll
        for (int j = 0; j < 4; j++)
            #pragma unroll
            for (int t = 0; t < 4; t++) acc[i][j][t] = 0.f;

    /* prologue: stages 0,1 */
    load_stage(sb + 0*STAGE3, A, Bh, Bl, m0, n0, 0, tid);
    load_stage(sb + 1*STAGE3, A, Bh, Bl, m0, n0, 1, tid);

    int bufc = 0;
    int bufn = 2;
    for (int kc = 0; kc < KITERS; kc++) {
        if (kc < KITERS-1) { CPWAIT(1); } else { CPWAIT(0); }
        __syncthreads();
        if (kc + 2 < KITERS)
            load_stage(sb + bufn*STAGE3, A, Bh, Bl, m0, n0, kc+2, tid);

        const uint32_t tb = sb + bufc*STAGE3;
        #pragma unroll
        for (int ks = 0; ks < 2; ks++) {
            const uint32_t kso = (uint32_t)(ks*32);   /* 16 fp16 = 32 B */
            uint32_t ah[4][4], bh[2][4], bl[2][4];
            #pragma unroll
            for (int mf = 0; mf < 4; mf++)
                LDSM4(ah[mf], tb + OFF_A + awarp + (uint32_t)(mf*16*ROWB) + kso + aoff);
            #pragma unroll
            for (int nb = 0; nb < 2; nb++) {
                LDSM4(bh[nb], tb + OFF_BH + bwarp + (uint32_t)(nb*16*ROWB) + kso + boff);
                LDSM4(bl[nb], tb + OFF_BL + bwarp + (uint32_t)(nb*16*ROWB) + kso + boff);
            }
            #pragma unroll
            for (int mf = 0; mf < 4; mf++)
                #pragma unroll
                for (int nb = 0; nb < 2; nb++) {
                    MMA(acc[mf][nb*2+0], ah[mf], bh[nb][0], bh[nb][1]);
                    MMA(acc[mf][nb*2+1], ah[mf], bh[nb][2], bh[nb][3]);
                    MMA(acc[mf][nb*2+0], ah[mf], bl[nb][0], bl[nb][1]);
                    MMA(acc[mf][nb*2+1], ah[mf], bl[nb][2], bl[nb][3]);
                }
        }
        bufc = (bufc == 2) ? 0 : bufc + 1;
        bufn = (bufn == 2) ? 0 : bufn + 1;
    }

    /* epilogue: scale + bias (+ split resid); fp32 or fp16 store */
    #pragma unroll
    for (int mf = 0; mf < 4; mf++) {
        #pragma unroll
        for (int half = 0; half < 2; half++) {
            const int row = m0 + wm*64 + mf*16 + half*8 + (l >> 2);
            const size_t ro = (size_t)row * Fdim;
            #pragma unroll
            for (int nf = 0; nf < 4; nf++) {
                const int col = n0 + wn*32 + nf*8 + (l & 3)*2;
                float2 o;
                o.x = acc[mf][nf][half*2+0]*INV_WSCALE + bias[col];
                o.y = acc[mf][nf][half*2+1]*INV_WSCALE + bias[col+1];
                if (residh) {
                    const __half2 rh = *(const __half2*)(residh + ro + col);
                    const __half2 rl = *(const __half2*)(residl + ro + col);
                    const float2 fh = __half22float2(rh);
                    const float2 fl = __half22float2(rl);
                    o.x += fh.x + fl.x; o.y += fh.y + fl.y;
                }
                if (Ch) {
                    *(__half2*)(Ch + ro + col) = __floats2half2_rn(o.x, o.y);
                } else {
                    *(float2*)(Cf + ro + col) = o;
                }
            }
        }
    }
}

__global__ __launch_bounds__(256, 2)
void qkv_gemm(const __half* __restrict__ xh,
              const __half* __restrict__ wh, const __half* __restrict__ wl,
              const float* __restrict__ bq, const float* __restrict__ bk,
              const float* __restrict__ bv,
              __half* __restrict__ Q, __half* __restrict__ K, float* __restrict__ V)
{
    const int z = blockIdx.z;
    const __half* Bh = wh + (size_t)z*WMAT;
    const __half* Bl = wl + (size_t)z*WMAT;
    const float* bias = (z == 0) ? bq : (z == 1) ? bk : bv;
    __half* Ch = (z == 0) ? Q : (z == 1) ? K : nullptr;
    float*  Cf = (z == 2) ? V : nullptr;
    gemm_mma(xh, Bh, Bl, bias, nullptr, nullptr, Cf, Ch);
}

__global__ __launch_bounds__(256, 2)
void ff_gemm(const __half* __restrict__ xh, const __half* __restrict__ xl,
             const __half* __restrict__ wh, const __half* __restrict__ wl,
             const float* __restrict__ bf, float* __restrict__ Y)
{
    gemm_mma(xh, wh, wl, bf, xh, xl, Y, nullptr);   /* resid = recombined x */
}

/* ------ one-shot weight transpose + scaled fp16 split: W[k,n] -> [n,k] ------ */
__global__ __launch_bounds__(256)
void wconv_kernel(const float* __restrict__ Wq, const float* __restrict__ Wk,
                  const float* __restrict__ Wv, const float* __restrict__ Wf,
                  __half* __restrict__ oh, __half* __restrict__ ol)
{
    __shared__ float tile[32][33];
    const int z = blockIdx.z, layer = z >> 2, mat = z & 3;
    const float* W = ((mat == 0) ? Wq : (mat == 1) ? Wk : (mat == 2) ? Wv : Wf)
                     + (size_t)layer*WMAT;
    const int kx = blockIdx.x*32, ny = blockIdx.y*32;
    const int ix = threadIdx.x & 31, iy = threadIdx.x >> 5;  /* 32 x 8 */
    #pragma unroll
    for (int j = 0; j < 4; j++)
        tile[iy + 8*j][ix] = W[(size_t)(kx + iy + 8*j)*Fdim + ny + ix];
    __syncthreads();
    __half* dh = oh + (size_t)z*WMAT;
    __half* dl = ol + (size_t)z*WMAT;
    #pragma unroll
    for (int j = 0; j < 4; j++) {
        const float v = tile[ix][iy + 8*j] * WSCALE;
        const __half h = __float2half(v);
        const float lo = v - __half2float(h);
        const size_t o = (size_t)(ny + iy + 8*j)*Fdim + kx + ix;
        dh[o] = h; dl[o] = __float2half(lo);
    }
}

/* ---------------- fp16 split store / recombine helpers ---------------- */
__device__ __forceinline__ void store_split4(__half* hi, __half* lo,
                                             size_t base, float4 o)
{
    const __half h0=__float2half(o.x), h1=__float2half(o.y),
                 h2=__float2half(o.z), h3=__float2half(o.w);
    __half2 hp0 = __halves2half2(h0,h1), hp1 = __halves2half2(h2,h3);
    __half2 lp0 = __halves2half2(__float2half(o.x-__half2float(h0)),
                                 __float2half(o.y-__half2float(h1)));
    __half2 lp1 = __halves2half2(__float2half(o.z-__half2float(h2)),
                                 __float2half(o.w-__half2float(h3)));
    uint2 hu, lu;
    hu.x = reinterpret_cast<uint32_t&>(hp0); hu.y = reinterpret_cast<uint32_t&>(hp1);
    lu.x = reinterpret_cast<uint32_t&>(lp0); lu.y = reinterpret_cast<uint32_t&>(lp1);
    *(uint2*)(hi + base) = hu; *(uint2*)(lo + base) = lu;
}

__device__ __forceinline__ float4 load_recombine4(const __half* hi,
                                                  const __half* lo, size_t base)
{
    const uint2 hu = *(const uint2*)(hi + base);
    const uint2 lu = *(const uint2*)(lo + base);
    const float2 f0 = __half22float2(reinterpret_cast<const __half2&>(hu.x));
    const float2 f1 = __half22float2(reinterpret_cast<const __half2&>(hu.y));
    const float2 g0 = __half22float2(reinterpret_cast<const __half2&>(lu.x));
    const float2 g1 = __half22float2(reinterpret_cast<const __half2&>(lu.y));
    return make_float4(f0.x+g0.x, f0.y+g0.y, f1.x+g1.x, f1.y+g1.y);
}

__device__ __forceinline__ float4 load_half4(const __half* p, size_t base)
{
    const uint2 u = *(const uint2*)(p + base);
    const float2 a = __half22float2(reinterpret_cast<const __half2&>(u.x));
    const float2 b = __half22float2(reinterpret_cast<const __half2&>(u.y));
    return make_float4(a.x, a.y, b.x, b.y);
}

/* ------- attention + residual + LN1, 2 tokens per 256-thread block ------- */
__global__ __launch_bounds__(256)
void attn_ln_kernel(const __half* __restrict__ Q, const __half* __restrict__ Km,
                    const float* __restrict__ V,
                    const float* __restrict__ gma, const float* __restrict__ bta,
                    __half* __restrict__ xh, __half* __restrict__ xl)
{
    __shared__ __align__(16) float sk[2][Fdim], sv[2][Fdim];
    __shared__ float red[2][2][4];
    const int tid = threadIdx.x;
    const int half = tid >> 7;
    const int t = tid & 127;
    const int m = blockIdx.x*2 + half;
    const size_t off = (size_t)m * Fdim;

    const float4 qreg = load_half4(Q, off + 4*t);
    ((float4*)sk[half])[t] = load_half4(Km, off + 4*t);
    ((float4*)sv[half])[t] = *(const float4*)(V + off + 4*t);
    const float4 xr = load_recombine4(xh, xl, off + 4*t);
    __syncthreads();

    const int dbase = (t & 15) * 4;
    float sc[Hh];
    #pragma unroll
    for (int g = 0; g < Hh; g++) {
        const float4 kv = *(const float4*)&sk[half][g*DHd + dbase];
        float d = qreg.x*kv.x + qreg.y*kv.y + qreg.z*kv.z + qreg.w*kv.w;
        d += __shfl_xor_sync(0xffffffffu, d, 1);
        d += __shfl_xor_sync(0xffffffffu, d, 2);
        d += __shfl_xor_sync(0xffffffffu, d, 4);
        d += __shfl_xor_sync(0xffffffffu, d, 8);
        sc[g] = d;
    }
    float mx = sc[0];
    #pragma unroll
    for (int g = 1; g < Hh; g++) mx = fmaxf(mx, sc[g]);
    float sum = 0.f;
    #pragma unroll
    for (int g = 0; g < Hh; g++) { sc[g] = __expf(sc[g] - mx); sum += sc[g]; }
    const float inv = 1.f / sum;

    float4 av = make_float4(0.f, 0.f, 0.f, 0.f);
    #pragma unroll
    for (int g = 0; g < Hh; g++) {
        const float w = sc[g] * inv;
        const float4 vv = *(const float4*)&sv[half][g*DHd + dbase];
        av.x += w*vv.x; av.y += w*vv.y; av.z += w*vv.z; av.w += w*vv.w;
    }
    const float v0 = av.x+xr.x, v1 = av.y+xr.y, v2 = av.z+xr.z, v3 = av.w+xr.w;

    float lsum = v0+v1+v2+v3, lsq = v0*v0+v1*v1+v2*v2+v3*v3;
    #pragma unroll
    for (int o = 16; o > 0; o >>= 1) {
        lsum += __shfl_xor_sync(0xffffffffu, lsum, o);
        lsq  += __shfl_xor_sync(0xffffffffu, lsq,  o);
    }
    if ((t & 31) == 0) { red[half][0][t>>5] = lsum; red[half][1][t>>5] = lsq; }
    __syncthreads();
    const float tsum = red[half][0][0]+red[half][0][1]+red[half][0][2]+red[half][0][3];
    const float tsq  = red[half][1][0]+red[half][1][1]+red[half][1][2]+red[half][1][3];
    const float mean = tsum * (1.f/Fdim);
    const float var  = tsq * (1.f/Fdim) - mean*mean;
    const float rstd = rsqrtf(var + EPSF);

    const float4 gm = *(const float4*)(gma + 4*t);
    const float4 bt = *(const float4*)(bta + 4*t);
    float4 o;
    o.x = (v0-mean)*rstd*gm.x + bt.x;
    o.y = (v1-mean)*rstd*gm.y + bt.y;
    o.z = (v2-mean)*rstd*gm.z + bt.z;
    o.w = (v3-mean)*rstd*gm.w + bt.w;
    store_split4(xh, xl, off + 4*t, o);
}

/* ---------------- LN2: y -> split x (or fp32 d_out on last layer) ------------- */
__global__ __launch_bounds__(128)
void ln_kernel(const float* __restrict__ Y, float* __restrict__ O,
               const float* __restrict__ gma, const float* __restrict__ bta,
               __half* __restrict__ xh, __half* __restrict__ xl)
{
    __shared__ float red[2][4];
    const int m = blockIdx.x, t = threadIdx.x;
    const size_t off = (size_t)m * Fdim;
    const float4 v = *(const float4*)(Y + off + 4*t);

    float lsum = v.x+v.y+v.z+v.w, lsq = v.x*v.x+v.y*v.y+v.z*v.z+v.w*v.w;
    #pragma unroll
    for (int o = 16; o > 0; o >>= 1) {
        lsum += __shfl_xor_sync(0xffffffffu, lsum, o);
        lsq  += __shfl_xor_sync(0xffffffffu, lsq,  o);
    }
    if ((t & 31) == 0) { red[0][t>>5] = lsum; red[1][t>>5] = lsq; }
    __syncthreads();
    const float tsum = red[0][0]+red[0][1]+red[0][2]+red[0][3];
    const float tsq  = red[1][0]+red[1][1]+red[1][2]+red[1][3];
    const float mean = tsum * (1.f/Fdim);
    const float var  = tsq * (1.f/Fdim) - mean*mean;
    const float rstd = rsqrtf(var + EPSF);

    const float4 gm = *(const float4*)(gma + 4*t);
    const float4 bt = *(const float4*)(bta + 4*t);
    float4 o;
    o.x = (v.x-mean)*rstd*gm.x + bt.x;
    o.y = (v.y-mean)*rstd*gm.y + bt.y;
    o.z = (v.z-mean)*rstd*gm.z + bt.z;
    o.w = (v.w-mean)*rstd*gm.w + bt.w;
    if (O) *(float4*)(O + off + 4*t) = o;
    if (xh) store_split4(xh, xl, off + 4*t, o);
}

/* ---------------- embedding + pos-enc -> split x ---------------- */
__global__ __launch_bounds__(128)
void embed_kernel(const int* __restrict__ text, const float* __restrict__ emb,
                  const float* __restrict__ pe,
                  __half* __restrict__ xh, __half* __restrict__ xl)
{
    const int m = blockIdx.x, t = threadIdx.x;
    const int tok = text[m];
    const int s = m & (Sseq - 1);
    const float4 e = *(const float4*)(emb + (size_t)tok*Fdim + 4*t);
    const float4 p = *(const float4*)(pe  + (size_t)s  *Fdim + 4*t);
    float4 o; o.x=e.x+p.x; o.y=e.y+p.y; o.z=e.z+p.z; o.w=e.w+p.w;
    store_split4(xh, xl, (size_t)m*Fdim + 4*t, o);
}

/* ---------------------------------------------------------------- */
extern "C" void kernel_launch(void* const* d_in, const int* in_sizes, int n_in,
                              void* d_out, int out_size)
{
    const int*   text  = (const int*)  d_in[0];
    const float* emb   = (const float*)d_in[1];
    const float* pe    = (const float*)d_in[2];
    const float* Wq    = (const float*)d_in[3];
    const float* bq    = (const float*)d_in[4];
    const float* Wk    = (const float*)d_in[5];
    const float* bk    = (const float*)d_in[6];
    const float* Wv    = (const float*)d_in[7];
    const float* bv    = (const float*)d_in[8];
    const float* g1    = (const float*)d_in[9];
    const float* beta1 = (const float*)d_in[10];
    const float* Wf    = (const float*)d_in[11];
    const float* bf    = (const float*)d_in[12];
    const float* g2    = (const float*)d_in[13];
    const float* beta2 = (const float*)d_in[14];

    float *v, *y;
    __half *q, *k, *xh, *xl, *wh, *wl;
    cudaGetSymbolAddress((void**)&q,  g_q);
    cudaGetSymbolAddress((void**)&k,  g_k);
    cudaGetSymbolAddress((void**)&v,  g_v);
    cudaGetSymbolAddress((void**)&y,  g_y);
    cudaGetSymbolAddress((void**)&xh, g_xh);
    cudaGetSymbolAddress((void**)&xl, g_xl);
    cudaGetSymbolAddress((void**)&wh, g_wh);
    cudaGetSymbolAddress((void**)&wl, g_wl);

    cudaFuncSetAttribute(qkv_gemm, cudaFuncAttributeMaxDynamicSharedMemorySize, GSMEM);
    cudaFuncSetAttribute(ff_gemm,  cudaFuncAttributeMaxDynamicSharedMemorySize, GSMEM);

    wconv_kernel<<<dim3(16,16,24), 256>>>(Wq, Wk, Wv, Wf, wh, wl);
    embed_kernel<<<MTOK, 128>>>(text, emb, pe, xh, xl);

    const dim3 gq(Fdim/128, MTOK/128, 3);
    const dim3 gf(Fdim/128, MTOK/128, 1);
    for (int i = 0; i < NLAYERS; i++) {
        const size_t wo = (size_t)i * 4 * WMAT;
        const size_t vo = (size_t)i * Fdim;
        const bool last = (i == NLAYERS-1);
        qkv_gemm<<<gq, 256, GSMEM>>>(xh, wh + wo, wl + wo,
                                     bq+vo, bk+vo, bv+vo, q, k, v);
        attn_ln_kernel<<<MTOK/2, 256>>>(q, k, v, g1+vo, beta1+vo, xh, xl);
        ff_gemm<<<gf, 256, GSMEM>>>(xh, xl, wh + wo + 3*(size_t)WMAT,
                                    wl + wo + 3*(size_t)WMAT, bf+vo, y);
        ln_kernel<<<MTOK, 128>>>(y, last ? (float*)d_out : nullptr, g2+vo, beta2+vo,
                                 last ? nullptr : xh, last ? nullptr : xl);
    }
}

// round 17
// speedup vs baseline: 1.0631x; 1.0024x over previous
#include <cuda_runtime.h>
#include <cuda_fp16.h>
#include <cstdint>

#define NLAYERS 6
#define Fdim 512
#define Hh 8
#define DHd 64
#define MTOK (64*512)        /* 32768 tokens */
#define Sseq 512
#define EPSF 1e-5f
#define WMAT (Fdim*Fdim)
#define WSCALE 256.0f
#define INV_WSCALE (1.0f/256.0f)

/* ---- warp-MMA GEMM config: 128x128 block, 8 warps of 64x32 (R13 proven) ---- */
#define BK 32
#define KITERS (Fdim/BK)     /* 16 */
#define ROWB 80              /* 32 fp16 = 64B data + 16B pad per row */
#define TILESM (128*ROWB)    /* 10240 B */
#define STAGE3 (3*TILESM)    /* A, Bh, Bl = 30720 B */
#define GSMEM (3*STAGE3)     /* 92160 B; x2 CTAs/SM = 184320 < 228KB */
#define OFF_A 0
#define OFF_BH TILESM
#define OFF_BL (2*TILESM)

/* ---- scratch (allocation-free) ---- */
__device__ __align__(256) __half g_q[MTOK*Fdim];   /* fp16 Q */
__device__ __align__(256) __half g_k[MTOK*Fdim];   /* fp16 K */
__device__ __align__(256) __half g_v[MTOK*Fdim];   /* fp16 V */
__device__ __align__(256) float  g_y[MTOK*Fdim];
__device__ __align__(256) __half g_xh[MTOK*Fdim];  /* fp16(x) — GEMM operand */
__device__ __align__(256) __half g_xl[MTOK*Fdim];  /* fp16(x - xh) — resid only */
__device__ __align__(256) __half g_wh[NLAYERS*4*WMAT];  /* fp16(256*W), [N,K] */
__device__ __align__(256) __half g_wl[NLAYERS*4*WMAT];  /* fp16(256*W - Wh)    */

/* ---------------- PTX helpers (all sm_80+ baseline) ---------------- */
#define CP16(s,g) asm volatile("cp.async.cg.shared.global [%0], [%1], 16;" \
                               :: "r"(s), "l"(g))
#define CPCOMMIT() asm volatile("cp.async.commit_group;" ::: "memory")
#define CPWAIT(n)  asm volatile("cp.async.wait_group %0;" :: "n"(n) : "memory")

#define LDSM4(r, a) \
    asm volatile("ldmatrix.sync.aligned.m8n8.x4.shared.b16 {%0,%1,%2,%3}, [%4];" \
        : "=r"((r)[0]), "=r"((r)[1]), "=r"((r)[2]), "=r"((r)[3]) : "r"(a))

#define MMA(c, a, b0, b1) \
    asm volatile("mma.sync.aligned.m16n8k16.row.col.f32.f16.f16.f32 " \
        "{%0,%1,%2,%3}, {%4,%5,%6,%7}, {%8,%9}, {%0,%1,%2,%3};" \
        : "+f"((c)[0]), "+f"((c)[1]), "+f"((c)[2]), "+f"((c)[3]) \
        : "r"((a)[0]), "r"((a)[1]), "r"((a)[2]), "r"((a)[3]), "r"(b0), "r"(b1))

/* ---------------- fp16 2-term warp-MMA GEMM ----------------
   out = (1/256) * A16[*,512] @ (Wh+Wl)^T + bias (+ recombined resid)
   Writes fp32 to Cf, or fp16 to Ch (exactly one non-null). */
__device__ __forceinline__ void load_stage(
    uint32_t tb, const __half* __restrict__ A,
    const __half* __restrict__ Bh, const __half* __restrict__ Bl,
    int m0, int n0, int kc, int tid)
{
    #pragma unroll
    for (int idx = tid; idx < 512; idx += 256) {
        const int r = idx >> 2, p = idx & 3;
        const uint32_t so = (uint32_t)(r*ROWB + p*16);
        const size_t ka = (size_t)(m0 + r)*Fdim + kc*BK + p*8;
        const size_t kb = (size_t)(n0 + r)*Fdim + kc*BK + p*8;
        CP16(tb + OFF_A  + so, A  + ka);
        CP16(tb + OFF_BH + so, Bh + kb);
        CP16(tb + OFF_BL + so, Bl + kb);
    }
    CPCOMMIT();
}

__device__ __forceinline__ void gemm_mma(
    const __half* __restrict__ A,
    const __half* __restrict__ Bh, const __half* __restrict__ Bl,
    const float* __restrict__ bias,
    const __half* __restrict__ residh, const __half* __restrict__ residl,
    float* __restrict__ Cf, __half* __restrict__ Ch)
{
    extern __shared__ char ds[];
    const uint32_t sb = (uint32_t)__cvta_generic_to_shared(ds);
    const int tid = threadIdx.x, l = tid & 31, wid = tid >> 5;
    const int wm = wid & 1, wn = wid >> 1;          /* warps: 2 (M) x 4 (N) */
    const int m0 = blockIdx.y * 128, n0 = blockIdx.x * 128;

    /* ldmatrix per-lane offsets */
    const uint32_t aoff = (uint32_t)((l & 15)*ROWB + (l >> 4)*16);
    const uint32_t boff = (uint32_t)(((l & 7) + ((l >> 4) << 3))*ROWB + ((l >> 3) & 1)*16);
    const uint32_t awarp = (uint32_t)(wm*64*ROWB);
    const uint32_t bwarp = (uint32_t)(wn*32*ROWB);

    float acc[4][4][4];
    #pragma unroll
    for (int i = 0; i < 4; i++)
        #pragma unroll
        for (int j = 0; j < 4; j++)
            #pragma unroll
            for (int t = 0; t < 4; t++) acc[i][j][t] = 0.f;

    /* prologue: stages 0,1 */
    load_stage(sb + 0*STAGE3, A, Bh, Bl, m0, n0, 0, tid);
    load_stage(sb + 1*STAGE3, A, Bh, Bl, m0, n0, 1, tid);

    int bufc = 0;
    int bufn = 2;
    for (int kc = 0; kc < KITERS; kc++) {
        if (kc < KITERS-1) { CPWAIT(1); } else { CPWAIT(0); }
        __syncthreads();
        if (kc + 2 < KITERS)
            load_stage(sb + bufn*STAGE3, A, Bh, Bl, m0, n0, kc+2, tid);

        const uint32_t tb = sb + bufc*STAGE3;
        #pragma unroll
        for (int ks = 0; ks < 2; ks++) {
            const uint32_t kso = (uint32_t)(ks*32);   /* 16 fp16 = 32 B */
            uint32_t ah[4][4], bh[2][4], bl[2][4];
            #pragma unroll
            for (int mf = 0; mf < 4; mf++)
                LDSM4(ah[mf], tb + OFF_A + awarp + (uint32_t)(mf*16*ROWB) + kso + aoff);
            #pragma unroll
            for (int nb = 0; nb < 2; nb++) {
                LDSM4(bh[nb], tb + OFF_BH + bwarp + (uint32_t)(nb*16*ROWB) + kso + boff);
                LDSM4(bl[nb], tb + OFF_BL + bwarp + (uint32_t)(nb*16*ROWB) + kso + boff);
            }
            #pragma unroll
            for (int mf = 0; mf < 4; mf++)
                #pragma unroll
                for (int nb = 0; nb < 2; nb++) {
                    MMA(acc[mf][nb*2+0], ah[mf], bh[nb][0], bh[nb][1]);
                    MMA(acc[mf][nb*2+1], ah[mf], bh[nb][2], bh[nb][3]);
                    MMA(acc[mf][nb*2+0], ah[mf], bl[nb][0], bl[nb][1]);
                    MMA(acc[mf][nb*2+1], ah[mf], bl[nb][2], bl[nb][3]);
                }
        }
        bufc = (bufc == 2) ? 0 : bufc + 1;
        bufn = (bufn == 2) ? 0 : bufn + 1;
    }

    /* epilogue: scale + bias (+ split resid); fp32 or fp16 store */
    #pragma unroll
    for (int mf = 0; mf < 4; mf++) {
        #pragma unroll
        for (int half = 0; half < 2; half++) {
            const int row = m0 + wm*64 + mf*16 + half*8 + (l >> 2);
            const size_t ro = (size_t)row * Fdim;
            #pragma unroll
            for (int nf = 0; nf < 4; nf++) {
                const int col = n0 + wn*32 + nf*8 + (l & 3)*2;
                float2 o;
                o.x = acc[mf][nf][half*2+0]*INV_WSCALE + bias[col];
                o.y = acc[mf][nf][half*2+1]*INV_WSCALE + bias[col+1];
                if (residh) {
                    const __half2 rh = *(const __half2*)(residh + ro + col);
                    const __half2 rl = *(const __half2*)(residl + ro + col);
                    const float2 fh = __half22float2(rh);
                    const float2 fl = __half22float2(rl);
                    o.x += fh.x + fl.x; o.y += fh.y + fl.y;
                }
                if (Ch) {
                    *(__half2*)(Ch + ro + col) = __floats2half2_rn(o.x, o.y);
                } else {
                    *(float2*)(Cf + ro + col) = o;
                }
            }
        }
    }
}

__global__ __launch_bounds__(256, 2)
void qkv_gemm(const __half* __restrict__ xh,
              const __half* __restrict__ wh, const __half* __restrict__ wl,
              const float* __restrict__ bq, const float* __restrict__ bk,
              const float* __restrict__ bv,
              __half* __restrict__ Q, __half* __restrict__ K, __half* __restrict__ V)
{
    const int z = blockIdx.z;
    const __half* Bh = wh + (size_t)z*WMAT;
    const __half* Bl = wl + (size_t)z*WMAT;
    const float* bias = (z == 0) ? bq : (z == 1) ? bk : bv;
    __half* Ch = (z == 0) ? Q : (z == 1) ? K : V;
    gemm_mma(xh, Bh, Bl, bias, nullptr, nullptr, nullptr, Ch);
}

__global__ __launch_bounds__(256, 2)
void ff_gemm(const __half* __restrict__ xh, const __half* __restrict__ xl,
             const __half* __restrict__ wh, const __half* __restrict__ wl,
             const float* __restrict__ bf, float* __restrict__ Y)
{
    gemm_mma(xh, wh, wl, bf, xh, xl, Y, nullptr);   /* resid = recombined x */
}

/* ------ one-shot weight transpose + scaled fp16 split: W[k,n] -> [n,k] ------ */
__global__ __launch_bounds__(256)
void wconv_kernel(const float* __restrict__ Wq, const float* __restrict__ Wk,
                  const float* __restrict__ Wv, const float* __restrict__ Wf,
                  __half* __restrict__ oh, __half* __restrict__ ol)
{
    __shared__ float tile[32][33];
    const int z = blockIdx.z, layer = z >> 2, mat = z & 3;
    const float* W = ((mat == 0) ? Wq : (mat == 1) ? Wk : (mat == 2) ? Wv : Wf)
                     + (size_t)layer*WMAT;
    const int kx = blockIdx.x*32, ny = blockIdx.y*32;
    const int ix = threadIdx.x & 31, iy = threadIdx.x >> 5;  /* 32 x 8 */
    #pragma unroll
    for (int j = 0; j < 4; j++)
        tile[iy + 8*j][ix] = W[(size_t)(kx + iy + 8*j)*Fdim + ny + ix];
    __syncthreads();
    __half* dh = oh + (size_t)z*WMAT;
    __half* dl = ol + (size_t)z*WMAT;
    #pragma unroll
    for (int j = 0; j < 4; j++) {
        const float v = tile[ix][iy + 8*j] * WSCALE;
        const __half h = __float2half(v);
        const float lo = v - __half2float(h);
        const size_t o = (size_t)(ny + iy + 8*j)*Fdim + kx + ix;
        dh[o] = h; dl[o] = __float2half(lo);
    }
}

/* ---------------- fp16 split store / recombine helpers ---------------- */
__device__ __forceinline__ void store_split4(__half* hi, __half* lo,
                                             size_t base, float4 o)
{
    const __half h0=__float2half(o.x), h1=__float2half(o.y),
                 h2=__float2half(o.z), h3=__float2half(o.w);
    __half2 hp0 = __halves2half2(h0,h1), hp1 = __halves2half2(h2,h3);
    __half2 lp0 = __halves2half2(__float2half(o.x-__half2float(h0)),
                                 __float2half(o.y-__half2float(h1)));
    __half2 lp1 = __halves2half2(__float2half(o.z-__half2float(h2)),
                                 __float2half(o.w-__half2float(h3)));
    uint2 hu, lu;
    hu.x = reinterpret_cast<uint32_t&>(hp0); hu.y = reinterpret_cast<uint32_t&>(hp1);
    lu.x = reinterpret_cast<uint32_t&>(lp0); lu.y = reinterpret_cast<uint32_t&>(lp1);
    *(uint2*)(hi + base) = hu; *(uint2*)(lo + base) = lu;
}

__device__ __forceinline__ float4 load_recombine4(const __half* hi,
                                                  const __half* lo, size_t base)
{
    const uint2 hu = *(const uint2*)(hi + base);
    const uint2 lu = *(const uint2*)(lo + base);
    const float2 f0 = __half22float2(reinterpret_cast<const __half2&>(hu.x));
    const float2 f1 = __half22float2(reinterpret_cast<const __half2&>(hu.y));
    const float2 g0 = __half22float2(reinterpret_cast<const __half2&>(lu.x));
    const float2 g1 = __half22float2(reinterpret_cast<const __half2&>(lu.y));
    return make_float4(f0.x+g0.x, f0.y+g0.y, f1.x+g1.x, f1.y+g1.y);
}

__device__ __forceinline__ float4 load_half4(const __half* p, size_t base)
{
    const uint2 u = *(const uint2*)(p + base);
    const float2 a = __half22float2(reinterpret_cast<const __half2&>(u.x));
    const float2 b = __half22float2(reinterpret_cast<const __half2&>(u.y));
    return make_float4(a.x, a.y, b.x, b.y);
}

/* ------- attention + residual + LN1, 2 tokens per 256-thread block ------- */
__global__ __launch_bounds__(256)
void attn_ln_kernel(const __half* __restrict__ Q, const __half* __restrict__ Km,
                    const __half* __restrict__ V,
                    const float* __restrict__ gma, const float* __restrict__ bta,
                    __half* __restrict__ xh, __half* __restrict__ xl)
{
    __shared__ __align__(16) float sk[2][Fdim], sv[2][Fdim];
    __shared__ float red[2][2][4];
    const int tid = threadIdx.x;
    const int half = tid >> 7;
    const int t = tid & 127;
    const int m = blockIdx.x*2 + half;
    const size_t off = (size_t)m * Fdim;

    const float4 qreg = load_half4(Q, off + 4*t);
    ((float4*)sk[half])[t] = load_half4(Km, off + 4*t);
    ((float4*)sv[half])[t] = load_half4(V, off + 4*t);
    const float4 xr = load_recombine4(xh, xl, off + 4*t);
    __syncthreads();

    const int dbase = (t & 15) * 4;
    float sc[Hh];
    #pragma unroll
    for (int g = 0; g < Hh; g++) {
        const float4 kv = *(const float4*)&sk[half][g*DHd + dbase];
        float d = qreg.x*kv.x + qreg.y*kv.y + qreg.z*kv.z + qreg.w*kv.w;
        d += __shfl_xor_sync(0xffffffffu, d, 1);
        d += __shfl_xor_sync(0xffffffffu, d, 2);
        d += __shfl_xor_sync(0xffffffffu, d, 4);
        d += __shfl_xor_sync(0xffffffffu, d, 8);
        sc[g] = d;
    }
    float mx = sc[0];
    #pragma unroll
    for (int g = 1; g < Hh; g++) mx = fmaxf(mx, sc[g]);
    float sum = 0.f;
    #pragma unroll
    for (int g = 0; g < Hh; g++) { sc[g] = __expf(sc[g] - mx); sum += sc[g]; }
    const float inv = 1.f / sum;

    float4 av = make_float4(0.f, 0.f, 0.f, 0.f);
    #pragma unroll
    for (int g = 0; g < Hh; g++) {
        const float w = sc[g] * inv;
        const float4 vv = *(const float4*)&sv[half][g*DHd + dbase];
        av.x += w*vv.x; av.y += w*vv.y; av.z += w*vv.z; av.w += w*vv.w;
    }
    const float v0 = av.x+xr.x, v1 = av.y+xr.y, v2 = av.z+xr.z, v3 = av.w+xr.w;

    float lsum = v0+v1+v2+v3, lsq = v0*v0+v1*v1+v2*v2+v3*v3;
    #pragma unroll
    for (int o = 16; o > 0; o >>= 1) {
        lsum += __shfl_xor_sync(0xffffffffu, lsum, o);
        lsq  += __shfl_xor_sync(0xffffffffu, lsq,  o);
    }
    if ((t & 31) == 0) { red[half][0][t>>5] = lsum; red[half][1][t>>5] = lsq; }
    __syncthreads();
    const float tsum = red[half][0][0]+red[half][0][1]+red[half][0][2]+red[half][0][3];
    const float tsq  = red[half][1][0]+red[half][1][1]+red[half][1][2]+red[half][1][3];
    const float mean = tsum * (1.f/Fdim);
    const float var  = tsq * (1.f/Fdim) - mean*mean;
    const float rstd = rsqrtf(var + EPSF);

    const float4 gm = *(const float4*)(gma + 4*t);
    const float4 bt = *(const float4*)(bta + 4*t);
    float4 o;
    o.x = (v0-mean)*rstd*gm.x + bt.x;
    o.y = (v1-mean)*rstd*gm.y + bt.y;
    o.z = (v2-mean)*rstd*gm.z + bt.z;
    o.w = (v3-mean)*rstd*gm.w + bt.w;
    store_split4(xh, xl, off + 4*t, o);
}

/* ---------------- LN2: y -> split x (or fp32 d_out on last layer) ------------- */
__global__ __launch_bounds__(128)
void ln_kernel(const float* __restrict__ Y, float* __restrict__ O,
               const float* __restrict__ gma, const float* __restrict__ bta,
               __half* __restrict__ xh, __half* __restrict__ xl)
{
    __shared__ float red[2][4];
    const int m = blockIdx.x, t = threadIdx.x;
    const size_t off = (size_t)m * Fdim;
    const float4 v = *(const float4*)(Y + off + 4*t);

    float lsum = v.x+v.y+v.z+v.w, lsq = v.x*v.x+v.y*v.y+v.z*v.z+v.w*v.w;
    #pragma unroll
    for (int o = 16; o > 0; o >>= 1) {
        lsum += __shfl_xor_sync(0xffffffffu, lsum, o);
        lsq  += __shfl_xor_sync(0xffffffffu, lsq,  o);
    }
    if ((t & 31) == 0) { red[0][t>>5] = lsum; red[1][t>>5] = lsq; }
    __syncthreads();
    const float tsum = red[0][0]+red[0][1]+red[0][2]+red[0][3];
    const float tsq  = red[1][0]+red[1][1]+red[1][2]+red[1][3];
    const float mean = tsum * (1.f/Fdim);
    const float var  = tsq * (1.f/Fdim) - mean*mean;
    const float rstd = rsqrtf(var + EPSF);

    const float4 gm = *(const float4*)(gma + 4*t);
    const float4 bt = *(const float4*)(bta + 4*t);
    float4 o;
    o.x = (v.x-mean)*rstd*gm.x + bt.x;
    o.y = (v.y-mean)*rstd*gm.y + bt.y;
    o.z = (v.z-mean)*rstd*gm.z + bt.z;
    o.w = (v.w-mean)*rstd*gm.w + bt.w;
    if (O) *(float4*)(O + off + 4*t) = o;
    if (xh) store_split4(xh, xl, off + 4*t, o);
}

/* ---------------- embedding + pos-enc -> split x ---------------- */
__global__ __launch_bounds__(128)
void embed_kernel(const int* __restrict__ text, const float* __restrict__ emb,
                  const float* __restrict__ pe,
                  __half* __restrict__ xh, __half* __restrict__ xl)
{
    const int m = blockIdx.x, t = threadIdx.x;
    const int tok = text[m];
    const int s = m & (Sseq - 1);
    const float4 e = *(const float4*)(emb + (size_t)tok*Fdim + 4*t);
    const float4 p = *(const float4*)(pe  + (size_t)s  *Fdim + 4*t);
    float4 o; o.x=e.x+p.x; o.y=e.y+p.y; o.z=e.z+p.z; o.w=e.w+p.w;
    store_split4(xh, xl, (size_t)m*Fdim + 4*t, o);
}

/* ---------------------------------------------------------------- */
extern "C" void kernel_launch(void* const* d_in, const int* in_sizes, int n_in,
                              void* d_out, int out_size)
{
    const int*   text  = (const int*)  d_in[0];
    const float* emb   = (const float*)d_in[1];
    const float* pe    = (const float*)d_in[2];
    const float* Wq    = (const float*)d_in[3];
    const float* bq    = (const float*)d_in[4];
    const float* Wk    = (const float*)d_in[5];
    const float* bk    = (const float*)d_in[6];
    const float* Wv    = (const float*)d_in[7];
    const float* bv    = (const float*)d_in[8];
    const float* g1    = (const float*)d_in[9];
    const float* beta1 = (const float*)d_in[10];
    const float* Wf    = (const float*)d_in[11];
    const float* bf    = (const float*)d_in[12];
    const float* g2    = (const float*)d_in[13];
    const float* beta2 = (const float*)d_in[14];

    float *y;
    __half *q, *k, *v, *xh, *xl, *wh, *wl;
    cudaGetSymbolAddress((void**)&q,  g_q);
    cudaGetSymbolAddress((void**)&k,  g_k);
    cudaGetSymbolAddress((void**)&v,  g_v);
    cudaGetSymbolAddress((void**)&y,  g_y);
    cudaGetSymbolAddress((void**)&xh, g_xh);
    cudaGetSymbolAddress((void**)&xl, g_xl);
    cudaGetSymbolAddress((void**)&wh, g_wh);
    cudaGetSymbolAddress((void**)&wl, g_wl);

    cudaFuncSetAttribute(qkv_gemm, cudaFuncAttributeMaxDynamicSharedMemorySize, GSMEM);
    cudaFuncSetAttribute(ff_gemm,  cudaFuncAttributeMaxDynamicSharedMemorySize, GSMEM);

    wconv_kernel<<<dim3(16,16,24), 256>>>(Wq, Wk, Wv, Wf, wh, wl);
    embed_kernel<<<MTOK, 128>>>(text, emb, pe, xh, xl);

    const dim3 gq(Fdim/128, MTOK/128, 3);
    const dim3 gf(Fdim/128, MTOK/128, 1);
    for (int i = 0; i < NLAYERS; i++) {
        const size_t wo = (size_t)i * 4 * WMAT;
        const size_t vo = (size_t)i * Fdim;
        const bool last = (i == NLAYERS-1);
        qkv_gemm<<<gq, 256, GSMEM>>>(xh, wh + wo, wl + wo,
                                     bq+vo, bk+vo, bv+vo, q, k, v);
        attn_ln_kernel<<<MTOK/2, 256>>>(q, k, v, g1+vo, beta1+vo, xh, xl);
        ff_gemm<<<gf, 256, GSMEM>>>(xh, xl, wh + wo + 3*(size_t)WMAT,
                                    wl + wo + 3*(size_t)WMAT, bf+vo, y);
        ln_kernel<<<MTOK, 128>>>(y, last ? (float*)d_out : nullptr, g2+vo, beta2+vo,
                                 last ? nullptr : xh, last ? nullptr : xl);
    }
}